// round 7
// baseline (speedup 1.0000x reference)
#include <cuda_runtime.h>
#include <cuda_bf16.h>
#include <math.h>

// Cox partial-likelihood loss, N=8192, CENSORING < 0 (gate == event).
//
// Exact O(N): fine bucket b(yt) (4096 buckets, monotone in yt):
//   S_m = T - pfx[b_m] + sum_{same-bucket j, yt_j >= yt_m} ef_j
//   loss = sum_m ev_m*(log S_m - pred_m) / sum_m ev_m
//
// K1: histogram exp-sums + per-bucket AoS slot records; the LAST block
//     (ticket) scans the 4096 bucket sums once -> g_pfx, g_total, and
//     re-zeros the histogram in the same pass.
// K2: per-element loss. All per-bucket loads (pfx, cnt, 4 slot LDG.128)
//     depend only on b -> issued together, ONE L2 round trip. i64
//     fixed-point reduce + ticketed finalize (self-resetting state).
// All cross-thread accumulation is u64/i64 (associative) -> bitwise
// deterministic despite nondeterministic atomic/slot ordering.

#define CN     8192
#define B      4096
#define NBLK   32
#define NT     256
#define PT     (B / NT)            // 16 buckets per scan thread
#define SLOTS  8                   // bucket occupancy ~Poisson(2)
#define BSCALE 409.6f              // B / 10.0
#define FXS    1099511627776.0f    // 2^40 exp fixed-point scale
#define ASCF   68719476736.0f      // 2^36 numerator fixed-point scale
#define PF(i)  ((i) + ((i) >> 4))  // smem pad: break 128B-stride conflicts

__device__ unsigned long long g_fine[B];        // zeroed by K1 scan block
__device__ unsigned long long g_pfx[B];         // inclusive prefix
__device__ unsigned long long g_total;
__device__ unsigned int       g_scnt[B];        // zeroed by K2 last block
__device__ unsigned int       g_head[B];        // overflow list; zeroed by K2
__device__ unsigned int       g_next[CN];
__device__ float4             g_slot[B * SLOTS];// {yt, pad, ef_lo, ef_hi}
__device__ unsigned int       g_tick  = 0;      // K1 ticket; reset by K1
__device__ unsigned long long g_acc_a = 0;      // i64 numerator (2^36 fx)
__device__ unsigned long long g_acc_w = 0;      // event count
__device__ unsigned int       g_done  = 0;      // K2 ticket; reset by K2

__device__ __forceinline__ int bucket_of(float yt)
{
    int b = (int)(yt * BSCALE);
    return b > (B - 1) ? (B - 1) : b;
}

__device__ __forceinline__ unsigned long long ef_of(float pr)
{
    return (unsigned long long)(expf(pr) * FXS);   // identical K1/K2
}

// ---------------- K1: histogram + slots, then single ticketed scan ----------
__global__ __launch_bounds__(NT) void hist_kernel(
    const float* __restrict__ pred,
    const float* __restrict__ ytime)
{
    __shared__ unsigned long long s_buf[B + (B >> 4)];
    __shared__ unsigned long long s_wt[8];
    __shared__ int                s_last;

    const int t = threadIdx.x;
    const int k = blockIdx.x * NT + t;

    const float yt = ytime[k];
    const unsigned long long ef = ef_of(pred[k]);
    const int b = bucket_of(yt);

    atomicAdd(&g_fine[b], ef);
    const unsigned int pos = atomicAdd(&g_scnt[b], 1u);
    if (pos < SLOTS) {
        float4 rec;
        rec.x = yt;
        rec.y = 0.0f;
        rec.z = __uint_as_float((unsigned int)(ef & 0xFFFFFFFFull));
        rec.w = __uint_as_float((unsigned int)(ef >> 32));
        g_slot[b * SLOTS + pos] = rec;             // one STG.128
    } else {                                       // ultra-rare overflow
        g_next[k] = atomicExch(&g_head[b], (unsigned int)(k + 1));
    }

    __threadfence();                               // publish this thread's work
    __syncthreads();                               // whole block published
    if (t == 0) s_last = (atomicAdd(&g_tick, 1u) == NBLK - 1) ? 1 : 0;
    __syncthreads();
    if (!s_last) return;

    // ---- last block: the ONLY scan of the 4096 bucket sums ----
    #pragma unroll
    for (int i = 0; i < PT; ++i) {
        const int idx = i * NT + t;                // coalesced
        s_buf[PF(idx)] = g_fine[idx];
        g_fine[idx] = 0ull;                        // re-arm for next replay
    }
    __syncthreads();

    const int lane = t & 31, wid = t >> 5;
    unsigned long long v[PT];
    unsigned long long run = 0ull;
    #pragma unroll
    for (int i = 0; i < PT; ++i) {                 // serial run of 16
        run += s_buf[PF(t * PT + i)];
        v[i] = run;
    }
    unsigned long long inc = run;
    #pragma unroll
    for (int o = 1; o < 32; o <<= 1) {
        const unsigned long long p = __shfl_up_sync(0xFFFFFFFFu, inc, o);
        if (lane >= o) inc += p;
    }
    if (lane == 31) s_wt[wid] = inc;
    __syncthreads();
    if (wid == 0 && lane < 8) {
        const unsigned long long w = s_wt[lane];
        unsigned long long iw = w;
        #pragma unroll
        for (int o = 1; o < 8; o <<= 1) {
            const unsigned long long p = __shfl_up_sync(0xFFu, iw, o);
            if (lane >= o) iw += p;
        }
        s_wt[lane] = iw - w;                       // exclusive warp base
    }
    __syncthreads();
    const unsigned long long base = s_wt[wid] + (inc - run);
    #pragma unroll
    for (int i = 0; i < PT; ++i)
        s_buf[PF(t * PT + i)] = base + v[i];       // inclusive pfx
    __syncthreads();
    #pragma unroll
    for (int i = 0; i < PT; ++i) {
        const int idx = i * NT + t;                // coalesced write-out
        g_pfx[idx] = s_buf[PF(idx)];
    }
    if (t == NT - 1) g_total = base + v[PT - 1];   // pfx[B-1]
    if (t == 0)      g_tick  = 0u;                 // re-arm K1 ticket
}

// ---------------- K2: per-element loss, one L2 round trip ----------------
__global__ __launch_bounds__(NT) void loss_kernel(
    const float* __restrict__ pred,
    const float* __restrict__ ytime,
    const int*   __restrict__ event,
    float*       __restrict__ out)
{
    __shared__ unsigned long long s_ra[8];
    __shared__ int                s_rw[8];
    __shared__ int                s_last;

    const int t = threadIdx.x;
    const int m = blockIdx.x * NT + t;
    const int lane = t & 31, wid = t >> 5;

    const float yt = ytime[m];
    const float pm = pred[m];
    const int   ev = event[m];
    const int   b  = bucket_of(yt);

    // all of these depend only on b / constants -> issued together
    const unsigned long long pfxb = g_pfx[b];
    const unsigned int       cnt  = g_scnt[b];
    const unsigned long long T    = g_total;
    const float4 s0 = g_slot[b * SLOTS + 0];
    const float4 s1 = g_slot[b * SLOTS + 1];
    const float4 s2 = g_slot[b * SLOTS + 2];
    const float4 s3 = g_slot[b * SLOTS + 3];

    unsigned long long S = T - pfxb;               // buckets strictly above

    #define ADDSLOT(r, j) do {                                              \
        if ((j) < cnt && (r).x >= yt)                                       \
            S += (unsigned long long)__float_as_uint((r).z)                 \
               | ((unsigned long long)__float_as_uint((r).w) << 32);        \
    } while (0)

    ADDSLOT(s0, 0u); ADDSLOT(s1, 1u); ADDSLOT(s2, 2u); ADDSLOT(s3, 3u);
    if (cnt > 4u) {                                // ~5% of lanes
        const float4 s4 = g_slot[b * SLOTS + 4];
        const float4 s5 = g_slot[b * SLOTS + 5];
        const float4 s6 = g_slot[b * SLOTS + 6];
        const float4 s7 = g_slot[b * SLOTS + 7];
        ADDSLOT(s4, 4u); ADDSLOT(s5, 5u); ADDSLOT(s6, 6u); ADDSLOT(s7, 7u);
        if (cnt > SLOTS) {                         // ~1 bucket in 4096
            for (unsigned int h = g_head[b]; h != 0u; ) {
                const unsigned int j = h - 1u;
                if (ytime[j] >= yt) S += ef_of(pred[j]);
                h = g_next[j];
            }
        }
    }
    #undef ADDSLOT

    const float Sf = (float)S * (1.0f / FXS);
    const float af = (float)ev * (logf(Sf) - pm);
    long long num = (long long)(af * ASCF);
    int       wct = ev;

    #pragma unroll
    for (int o = 16; o > 0; o >>= 1) {
        num += __shfl_xor_sync(0xFFFFFFFFu, num, o);
        wct += __shfl_xor_sync(0xFFFFFFFFu, wct, o);
    }
    if (lane == 0) { s_ra[wid] = (unsigned long long)num; s_rw[wid] = wct; }
    __syncthreads();

    if (t == 0) {
        long long nb = 0; int wb = 0;
        #pragma unroll
        for (int i = 0; i < 8; ++i) { nb += (long long)s_ra[i]; wb += s_rw[i]; }
        atomicAdd(&g_acc_a, (unsigned long long)nb);
        atomicAdd(&g_acc_w, (unsigned long long)wb);
        __threadfence();
        s_last = (atomicAdd(&g_done, 1u) == NBLK - 1) ? 1 : 0;
    }
    __syncthreads();

    if (s_last) {
        if (t == 0) {
            const long long ai = (long long)atomicAdd(&g_acc_a, 0ull);
            const long long wi = (long long)atomicAdd(&g_acc_w, 0ull);
            out[0] = (float)(((double)ai / (double)ASCF) / (double)wi);
            atomicExch(&g_acc_a, 0ull);
            atomicExch(&g_acc_w, 0ull);
            atomicExch(&g_done, 0u);
        }
        for (int i = t; i < B; i += NT) {          // re-arm for next replay
            g_scnt[i] = 0u;
            g_head[i] = 0u;
        }
    }
}

extern "C" void kernel_launch(void* const* d_in, const int* in_sizes, int n_in,
                              void* d_out, int out_size)
{
    const float* pred  = (const float*)d_in[0];
    const float* ytime = (const float*)d_in[1];
    const int*   event = (const int*)d_in[2];
    float*       out   = (float*)d_out;

    hist_kernel<<<NBLK, NT>>>(pred, ytime);
    loss_kernel<<<NBLK, NT>>>(pred, ytime, event, out);
}